// round 12
// baseline (speedup 1.0000x reference)
#include <cuda_runtime.h>
#include <cstdint>

// Problem constants
#define B_  8
#define K_  65536
#define C_  128
#define N_  1024
#define CL  8                 // CTAs (cluster) per batch
#define PTS (K_/CL)           // 8192 points per CTA
#define TPB 512
#define PPT (PTS/TPB)         // 16 points per thread
#define NW  (TPB/32)          // 16 warps

// Output layout: [ new_xyz (B,N,3) | new_features (B,C,N) | sample_inds (B,N) ], float32
#define OXYZ  0
#define OFEAT (B_*N_*3)
#define OIND  (OFEAT + B_*C_*N_)

__device__ int g_inds[B_*N_];
__device__ unsigned g_epoch;     // bumped once per launch: graph-replay-safe tags

static __device__ __forceinline__ uint32_t cvta_s(const void* p){
  return (uint32_t)__cvta_generic_to_shared(p);
}
static __device__ __forceinline__ uint32_t mapa_rank(uint32_t a, uint32_t r){
  uint32_t o; asm("mapa.shared::cluster.u32 %0, %1, %2;" : "=r"(o) : "r"(a), "r"(r)); return o;
}
static __device__ __forceinline__ void st_cl_v4(uint32_t a, uint32_t x0, uint32_t x1,
                                                uint32_t x2, uint32_t x3){
  asm volatile("st.shared::cluster.v4.b32 [%0], {%1,%2,%3,%4};"
               :: "r"(a), "r"(x0), "r"(x1), "r"(x2), "r"(x3) : "memory");
}
static __device__ __forceinline__ uint4 ld_s_v4_vol(uint32_t a){
  uint4 v;
  asm volatile("ld.volatile.shared.v4.u32 {%0,%1,%2,%3}, [%4];"
               : "=r"(v.x), "=r"(v.y), "=r"(v.z), "=r"(v.w) : "r"(a) : "memory");
  return v;
}
static __device__ __forceinline__ void cluster_sync_(){
  asm volatile("barrier.cluster.arrive.aligned;" ::: "memory");
  asm volatile("barrier.cluster.wait.aligned;" ::: "memory");
}

// Warp-wide (dist,idx) argmax via two REDUX ops; min index wins ties (jnp.argmax).
static __device__ __forceinline__ void warp_argmax(uint32_t dbits, uint32_t idx,
                                                   uint32_t& out_d, uint32_t& out_i){
  uint32_t wmax = __reduce_max_sync(0xffffffffu, dbits);
  uint32_t cand = (dbits == wmax) ? idx : 0xffffffffu;
  out_i = __reduce_min_sync(0xffffffffu, cand);
  out_d = wmax;
}

// One 8-CTA cluster per batch. Points + running min-dist register-resident.
// Per iteration:
//  1) scalar distance update (exact unfused (dx^2+dy^2)+dz^2) + per-thread argmax
//  2) REDUX warp argmax; lane0 atomicMax(u64 key = distbits<<32 | ~idx) into a
//     double-buffered smem accumulator (staggered, hidden in warp arrival spread)
//  3) __syncthreads; warp0 loads the final key (one broadcast LDS) and lanes
//     0..7 ship two tag-validated 16B packets {tag,dist,idx,x} {tag,y,z,0}
//     to every CTA's slot (st.shared::cluster.v4 — no mbarrier)
//  4) ALL warps spin on local smem tags (volatile LDS), REDUX the 8 slots,
//     shfl winner coords from owning lane. Double-buffered; epoch-tagged.
__global__ void __launch_bounds__(TPB,1) __cluster_dims__(CL,1,1)
fps_kernel(const float* __restrict__ xyz, float* __restrict__ out)
{
  extern __shared__ float spts[];               // 3*PTS floats = 96KB (idx->coords)
  __shared__ unsigned long long accum[2];       // double-buffered CTA argmax key
  __shared__ uint4 slots[2][CL][2];             // [buf][src_rank][half] 16B packets

  const int tid  = threadIdx.x;
  const int lane = tid & 31;
  const int w    = tid >> 5;
  const int b    = blockIdx.x / CL;
  const int rank = blockIdx.x % CL;
  const float* xb = xyz + (size_t)b * K_ * 3;
  const int pbase = rank * PTS;
  const unsigned epoch = g_epoch;               // constant per launch

  if (rank == 0 && tid == 0){
    size_t o = (size_t)b * N_;
    out[OXYZ + o*3 + 0] = xb[0];
    out[OXYZ + o*3 + 1] = xb[1];
    out[OXYZ + o*3 + 2] = xb[2];
    out[OIND + o] = 0.0f;
    g_inds[o] = 0;
  }
  // invalidate slot tags (never matches any (epoch<<11)|t); zero accumulators
  if (tid < 2*CL*2) ((uint4*)slots)[tid] = make_uint4(0xffffffffu,0,0,0);
  if (tid == 0){ accum[0] = 0ull; accum[1] = 0ull; }

  // smem copy of this CTA's points (coalesced) for O(1) idx->coords lookup
  for (int i = tid; i < 3*PTS; i += TPB) spts[i] = xb[pbase*3 + i];

  // register-resident points + running distances
  float px[PPT], py[PPT], pz[PPT], dist[PPT];
#pragma unroll
  for (int j = 0; j < PPT; j++){
    int p = pbase + j*TPB + tid;
    px[j] = xb[3*p + 0];
    py[j] = xb[3*p + 1];
    pz[j] = xb[3*p + 2];
    dist[j] = 1e10f;
  }
  float cx = xb[0], cy = xb[1], cz = xb[2];     // first pick = index 0

  __syncthreads();
  cluster_sync_();   // slot-tag/accum init visible cluster-wide before remote stores

  // warp0 lanes 0..7: remote packet addresses in CTA `lane` (buf 0)
  uint32_t r_slot = 0;
  if (w == 0 && lane < CL)
    r_slot = mapa_rank(cvta_s(&slots[0][rank][0]), (uint32_t)lane);
  const uint32_t l_slot = cvta_s(&slots[0][0][0]) + (uint32_t)(lane & (CL-1)) * 32;

  for (int t = 1; t < N_; t++){
    const uint32_t buf = (uint32_t)(t & 1);
    const uint32_t tag = (epoch << 11) | (uint32_t)t;

    // ---- 1) distance update (exact: unfused rn mul/add, matches reference) ----
#pragma unroll
    for (int j = 0; j < PPT; j++){
      float dx = px[j] - cx, dy = py[j] - cy, dz = pz[j] - cz;
      float d = __fadd_rn(__fadd_rn(__fmul_rn(dx,dx), __fmul_rn(dy,dy)),
                          __fmul_rn(dz,dz));
      dist[j] = fminf(dist[j], d);
    }
    // per-thread max (pairwise tree) + descending eq-scan (lowest idx on tie)
    float m01 = fmaxf(dist[0], dist[1]),   m23 = fmaxf(dist[2], dist[3]);
    float m45 = fmaxf(dist[4], dist[5]),   m67 = fmaxf(dist[6], dist[7]);
    float m89 = fmaxf(dist[8], dist[9]),   mab = fmaxf(dist[10], dist[11]);
    float mcd = fmaxf(dist[12], dist[13]), mef = fmaxf(dist[14], dist[15]);
    float q0 = fmaxf(m01, m23), q1 = fmaxf(m45, m67);
    float q2 = fmaxf(m89, mab), q3 = fmaxf(mcd, mef);
    const float m = fmaxf(fmaxf(q0, q1), fmaxf(q2, q3));
    int loc = 0;
#pragma unroll
    for (int j = PPT-1; j >= 0; j--) if (dist[j] == m) loc = j*TPB + tid;

    // ---- 2) warp argmax + staggered smem atomic CTA-reduce ----
    uint32_t wD, wI;
    warp_argmax(__float_as_uint(m), (uint32_t)(pbase + loc), wD, wI);
    if (lane == 0)
      atomicMax(&accum[buf],
                ((unsigned long long)wD << 32) | (uint32_t)~wI);
    __syncthreads();

    // ---- 3) warp0: read final key + all-to-all packet ship ----
    if (w == 0){
      unsigned long long key = accum[buf];      // broadcast LDS (all lanes, same addr)
      __syncwarp();
      if (lane == 0) accum[buf] = 0ull;         // reset for t+2 (ordered by bar at t+1)
      uint32_t cD = (uint32_t)(key >> 32);
      uint32_t cI = ~(uint32_t)key;
      int lcl = (int)cI - pbase;                // CTA winner, local offset
      if (lane < CL){
        uint32_t X = __float_as_uint(spts[3*lcl + 0]);
        uint32_t Y = __float_as_uint(spts[3*lcl + 1]);
        uint32_t Z = __float_as_uint(spts[3*lcl + 2]);
        uint32_t a = r_slot + buf * (uint32_t)(CL * 32);
        st_cl_v4(a,      tag, cD, cI, X);
        st_cl_v4(a + 16, tag, Y,  Z,  0u);
      }
    }

    // ---- 4) all warps: spin on local tags, reduce 8 slots, pick winner ----
    const uint32_t pa = l_slot + buf * (uint32_t)(CL * 32);
    uint4 h0, h1;
    bool need = (lane < CL);
    bool r0 = !need, r1 = !need;
    do {
      if (!r0){ h0 = ld_s_v4_vol(pa);      r0 = (h0.x == tag); }
      if (!r1){ h1 = ld_s_v4_vol(pa + 16); r1 = (h1.x == tag); }
    } while (__any_sync(0xffffffffu, !(r0 && r1)));

    uint32_t db = need ? h0.y : 0u;
    uint32_t ix = need ? h0.z : 0xffffffffu;
    uint32_t gD, gI;
    warp_argmax(db, ix, gD, gI);
    const int s = (int)(gI >> 13);              // owning rank (PTS = 8192)
    cx = __uint_as_float(__shfl_sync(0xffffffffu, h0.w, s));
    cy = __uint_as_float(__shfl_sync(0xffffffffu, h1.y, s));
    cz = __uint_as_float(__shfl_sync(0xffffffffu, h1.z, s));

    // outputs from the LAST warp (keeps warp0 — next iter's shipper — lean)
    if (rank == 0 && w == NW-1 && lane == 0){
      size_t o = (size_t)b * N_ + t;
      out[OXYZ + o*3 + 0] = cx;
      out[OXYZ + o*3 + 1] = cy;
      out[OXYZ + o*3 + 2] = cz;
      out[OIND + o] = (float)gI;
      g_inds[o] = (int)gI;
    }
  }
  cluster_sync_();   // no CTA exits with remote stores possibly in flight
}

// Feature gather: out[b][c][t] = feat[b][c][ inds[b][t] ]
__global__ void gather_kernel(const float* __restrict__ feat, float* __restrict__ out)
{
  int i = blockIdx.x * blockDim.x + threadIdx.x;   // b*C*N + c*N + t
  int t  = i & (N_ - 1);
  int bc = i >> 10;            // b*C + c
  int bb = bc >> 7;            // / C_
  int idx = g_inds[bb * N_ + t];
  out[OFEAT + i] = feat[(size_t)bc * K_ + idx];
}

// Bump the epoch so packet tags never collide across graph replays.
__global__ void bump_epoch_kernel(){ g_epoch = g_epoch + 1u; }

extern "C" void kernel_launch(void* const* d_in, const int* in_sizes, int n_in,
                              void* d_out, int out_size)
{
  const float* xyz  = (const float*)d_in[0];   // (B,K,3)
  const float* feat = (const float*)d_in[1];   // (B,C,K)
  float* out = (float*)d_out;

  static int smem_set = 0;
  if (!smem_set){
    cudaFuncSetAttribute(fps_kernel, cudaFuncAttributeMaxDynamicSharedMemorySize,
                         3*PTS*(int)sizeof(float));
    smem_set = 1;
  }

  bump_epoch_kernel<<<1,1>>>();
  fps_kernel<<<B_ * CL, TPB, 3*PTS*sizeof(float)>>>(xyz, out);
  gather_kernel<<<(B_ * C_ * N_) / 256, 256>>>(feat, out);
}

// round 13
// speedup vs baseline: 1.2266x; 1.2266x over previous
#include <cuda_runtime.h>
#include <cstdint>

// Problem constants
#define B_  8
#define K_  65536
#define C_  128
#define N_  1024
#define CL  8                 // CTAs (cluster) per batch
#define PTS (K_/CL)           // 8192 points per CTA
#define TPB 512
#define PPT (PTS/TPB)         // 16 points per thread
#define NPR (PPT/2)           // 8 packed point-pairs per thread
#define NW  (TPB/32)          // 16 warps

// Output layout: [ new_xyz (B,N,3) | new_features (B,C,N) | sample_inds (B,N) ], float32
#define OXYZ  0
#define OFEAT (B_*N_*3)
#define OIND  (OFEAT + B_*C_*N_)

__device__ int g_inds[B_*N_];
__device__ unsigned g_epoch;     // bumped once per launch: graph-replay-safe tags

static __device__ __forceinline__ uint32_t cvta_s(const void* p){
  return (uint32_t)__cvta_generic_to_shared(p);
}
static __device__ __forceinline__ uint32_t mapa_rank(uint32_t a, uint32_t r){
  uint32_t o; asm("mapa.shared::cluster.u32 %0, %1, %2;" : "=r"(o) : "r"(a), "r"(r)); return o;
}
static __device__ __forceinline__ void st_cl_v4(uint32_t a, uint32_t x0, uint32_t x1,
                                                uint32_t x2, uint32_t x3){
  asm volatile("st.shared::cluster.v4.b32 [%0], {%1,%2,%3,%4};"
               :: "r"(a), "r"(x0), "r"(x1), "r"(x2), "r"(x3) : "memory");
}
static __device__ __forceinline__ uint4 ld_s_v4_vol(uint32_t a){
  uint4 v;
  asm volatile("ld.volatile.shared.v4.u32 {%0,%1,%2,%3}, [%4];"
               : "=r"(v.x), "=r"(v.y), "=r"(v.z), "=r"(v.w) : "r"(a) : "memory");
  return v;
}
static __device__ __forceinline__ void cluster_sync_(){
  asm volatile("barrier.cluster.arrive.aligned;" ::: "memory");
  asm volatile("barrier.cluster.wait.aligned;" ::: "memory");
}

// Packed f32x2 FMA (sm_103a FFMA2 — the one packed fp32 op that exists in HW).
// fma.rn per lane: round once. Used ONLY in bit-exact identity forms:
//   sub: fma(p, 1, -c) ; square: fma(d, d, +0) ; add: fma(a, 1, b)
#define FMAX2(o,a,b,c) asm("fma.rn.f32x2 %0, %1, %2, %3;" \
                           : "=l"(o) : "l"(a), "l"(b), "l"(c))
static __device__ __forceinline__ unsigned long long packx2(uint32_t lo, uint32_t hi){
  unsigned long long o; asm("mov.b64 %0, {%1, %2};" : "=l"(o) : "r"(lo), "r"(hi)); return o;
}
static __device__ __forceinline__ void unpackx2(uint32_t& lo, uint32_t& hi,
                                                unsigned long long v){
  asm("mov.b64 {%0, %1}, %2;" : "=r"(lo), "=r"(hi) : "l"(v));
}

// Warp-wide (dist,idx) argmax via two REDUX ops; min index wins ties (jnp.argmax).
static __device__ __forceinline__ void warp_argmax(uint32_t dbits, uint32_t idx,
                                                   uint32_t& out_d, uint32_t& out_i){
  uint32_t wmax = __reduce_max_sync(0xffffffffu, dbits);
  uint32_t cand = (dbits == wmax) ? idx : 0xffffffffu;
  out_i = __reduce_min_sync(0xffffffffu, cand);
  out_d = wmax;
}

// One 8-CTA cluster per batch. Point pairs + running min-dist register-resident.
// Per iteration:
//  1) FFMA2-packed distance update (bit-exact identities above) + per-thread argmax
//  2) REDUX warp argmax -> smem; __syncthreads
//  3) warp0: REDUX over 16 warp candidates; lanes 0..7 ship two tag-validated
//     16B packets {tag,dist,idx,x} {tag,y,z,0} to every CTA's slot
//     (st.shared::cluster.v4 — no mbarrier)
//  4) ALL warps spin on local smem tags (volatile LDS), REDUX the 8 slots,
//     shfl winner coords from owning lane. Double-buffered; epoch-tagged.
__global__ void __launch_bounds__(TPB,1) __cluster_dims__(CL,1,1)
fps_kernel(const float* __restrict__ xyz, float* __restrict__ out)
{
  extern __shared__ float spts[];               // 3*PTS floats = 96KB (idx->coords)
  __shared__ uint32_t wd[NW], wi[NW];           // per-warp candidates
  __shared__ uint4 slots[2][CL][2];             // [buf][src_rank][half] 16B packets

  const int tid  = threadIdx.x;
  const int lane = tid & 31;
  const int w    = tid >> 5;
  const int b    = blockIdx.x / CL;
  const int rank = blockIdx.x % CL;
  const float* xb = xyz + (size_t)b * K_ * 3;
  const int pbase = rank * PTS;
  const unsigned epoch = g_epoch;               // constant per launch

  if (rank == 0 && tid == 0){
    size_t o = (size_t)b * N_;
    out[OXYZ + o*3 + 0] = xb[0];
    out[OXYZ + o*3 + 1] = xb[1];
    out[OXYZ + o*3 + 2] = xb[2];
    out[OIND + o] = 0.0f;
    g_inds[o] = 0;
  }
  // invalidate slot tags (never matches any (epoch<<11)|t)
  if (tid < 2*CL*2) ((uint4*)slots)[tid] = make_uint4(0xffffffffu,0,0,0);

  // smem copy of this CTA's points (coalesced) for O(1) idx->coords lookup
  for (int i = tid; i < 3*PTS; i += TPB) spts[i] = xb[pbase*3 + i];

  // register-resident packed point pairs + scalar running distances
  unsigned long long pxp[NPR], pyp[NPR], pzp[NPR];
  float dist[PPT];
#pragma unroll
  for (int i = 0; i < NPR; i++){
    int p0 = pbase + (2*i)*TPB + tid;
    int p1 = p0 + TPB;
    pxp[i] = packx2(__float_as_uint(xb[3*p0+0]), __float_as_uint(xb[3*p1+0]));
    pyp[i] = packx2(__float_as_uint(xb[3*p0+1]), __float_as_uint(xb[3*p1+1]));
    pzp[i] = packx2(__float_as_uint(xb[3*p0+2]), __float_as_uint(xb[3*p1+2]));
    dist[2*i] = 1e10f; dist[2*i+1] = 1e10f;
  }
  float cx = xb[0], cy = xb[1], cz = xb[2];     // first pick = index 0

  __syncthreads();
  cluster_sync_();   // slot-tag init visible cluster-wide before any remote store

  // warp0 lanes 0..7: remote packet addresses in CTA `lane` (buf 0)
  uint32_t r_slot = 0;
  if (w == 0 && lane < CL)
    r_slot = mapa_rank(cvta_s(&slots[0][rank][0]), (uint32_t)lane);
  const uint32_t l_slot = cvta_s(&slots[0][0][0]) + (uint32_t)(lane & (CL-1)) * 32;

  const unsigned long long onep  = packx2(0x3f800000u, 0x3f800000u);   // {1,1}
  const unsigned long long zerop = 0ull;                               // {+0,+0}

  for (int t = 1; t < N_; t++){
    const uint32_t buf = (uint32_t)(t & 1);
    const uint32_t tag = (epoch << 11) | (uint32_t)t;

    // ---- 1) FFMA2 distance update (bit-exact: see identity notes above) ----
    const uint32_t ncx = __float_as_uint(-cx);
    const uint32_t ncy = __float_as_uint(-cy);
    const uint32_t ncz = __float_as_uint(-cz);
    const unsigned long long ncxp = packx2(ncx, ncx);
    const unsigned long long ncyp = packx2(ncy, ncy);
    const unsigned long long nczp = packx2(ncz, ncz);
#pragma unroll
    for (int i = 0; i < NPR; i++){
      unsigned long long dxp, dyp, dzp, sx, sy, sz, s1, d2;
      FMAX2(dxp, pxp[i], onep, ncxp);   // px - cx
      FMAX2(dyp, pyp[i], onep, ncyp);   // py - cy
      FMAX2(dzp, pzp[i], onep, nczp);   // pz - cz
      FMAX2(sx,  dxp, dxp, zerop);      // dx^2
      FMAX2(sy,  dyp, dyp, zerop);      // dy^2
      FMAX2(sz,  dzp, dzp, zerop);      // dz^2
      FMAX2(s1,  sx,  onep, sy);        // dx^2 + dy^2
      FMAX2(d2,  s1,  onep, sz);        // + dz^2
      uint32_t dlo, dhi; unpackx2(dlo, dhi, d2);
      dist[2*i]   = fminf(dist[2*i],   __uint_as_float(dlo));
      dist[2*i+1] = fminf(dist[2*i+1], __uint_as_float(dhi));
    }
    // per-thread max (pairwise tree) + descending eq-scan (lowest idx on tie)
    float m01 = fmaxf(dist[0], dist[1]),   m23 = fmaxf(dist[2], dist[3]);
    float m45 = fmaxf(dist[4], dist[5]),   m67 = fmaxf(dist[6], dist[7]);
    float m89 = fmaxf(dist[8], dist[9]),   mab = fmaxf(dist[10], dist[11]);
    float mcd = fmaxf(dist[12], dist[13]), mef = fmaxf(dist[14], dist[15]);
    float q0 = fmaxf(m01, m23), q1 = fmaxf(m45, m67);
    float q2 = fmaxf(m89, mab), q3 = fmaxf(mcd, mef);
    const float m = fmaxf(fmaxf(q0, q1), fmaxf(q2, q3));
    int loc = 0;
#pragma unroll
    for (int j = PPT-1; j >= 0; j--) if (dist[j] == m) loc = j*TPB + tid;

    // ---- 2) warp argmax via REDUX ----
    uint32_t wD, wI;
    warp_argmax(__float_as_uint(m), (uint32_t)(pbase + loc), wD, wI);
    if (lane == 0){ wd[w] = wD; wi[w] = wI; }
    __syncthreads();

    // ---- 3) warp0: CTA reduce + all-to-all packet ship (no barrier ops) ----
    if (w == 0){
      uint32_t cD, cI;
      warp_argmax(wd[lane & (NW-1)], wi[lane & (NW-1)], cD, cI);
      int lcl = (int)cI - pbase;                // CTA winner, local offset
      if (lane < CL){
        uint32_t X = __float_as_uint(spts[3*lcl + 0]);
        uint32_t Y = __float_as_uint(spts[3*lcl + 1]);
        uint32_t Z = __float_as_uint(spts[3*lcl + 2]);
        uint32_t a = r_slot + buf * (uint32_t)(CL * 32);
        st_cl_v4(a,      tag, cD, cI, X);
        st_cl_v4(a + 16, tag, Y,  Z,  0u);
      }
    }

    // ---- 4) all warps: spin on local tags, reduce 8 slots, pick winner ----
    const uint32_t pa = l_slot + buf * (uint32_t)(CL * 32);
    uint4 h0, h1;
    bool need = (lane < CL);
    bool r0 = !need, r1 = !need;
    do {
      if (!r0){ h0 = ld_s_v4_vol(pa);      r0 = (h0.x == tag); }
      if (!r1){ h1 = ld_s_v4_vol(pa + 16); r1 = (h1.x == tag); }
    } while (__any_sync(0xffffffffu, !(r0 && r1)));

    uint32_t db = need ? h0.y : 0u;
    uint32_t ix = need ? h0.z : 0xffffffffu;
    uint32_t gD, gI;
    warp_argmax(db, ix, gD, gI);
    const int s = (int)(gI >> 13);              // owning rank (PTS = 8192)
    cx = __uint_as_float(__shfl_sync(0xffffffffu, h0.w, s));
    cy = __uint_as_float(__shfl_sync(0xffffffffu, h1.y, s));
    cz = __uint_as_float(__shfl_sync(0xffffffffu, h1.z, s));

    if (rank == 0 && w == NW-1 && lane == 0){   // off the serial chain
      size_t o = (size_t)b * N_ + t;
      out[OXYZ + o*3 + 0] = cx;
      out[OXYZ + o*3 + 1] = cy;
      out[OXYZ + o*3 + 2] = cz;
      out[OIND + o] = (float)gI;
      g_inds[o] = (int)gI;
    }
  }
  cluster_sync_();   // no CTA exits with remote stores possibly in flight
}

// Feature gather: out[b][c][t] = feat[b][c][ inds[b][t] ]
__global__ void gather_kernel(const float* __restrict__ feat, float* __restrict__ out)
{
  int i = blockIdx.x * blockDim.x + threadIdx.x;   // b*C*N + c*N + t
  int t  = i & (N_ - 1);
  int bc = i >> 10;            // b*C + c
  int bb = bc >> 7;            // / C_
  int idx = g_inds[bb * N_ + t];
  out[OFEAT + i] = feat[(size_t)bc * K_ + idx];
}

// Bump the epoch so packet tags never collide across graph replays.
__global__ void bump_epoch_kernel(){ g_epoch = g_epoch + 1u; }

extern "C" void kernel_launch(void* const* d_in, const int* in_sizes, int n_in,
                              void* d_out, int out_size)
{
  const float* xyz  = (const float*)d_in[0];   // (B,K,3)
  const float* feat = (const float*)d_in[1];   // (B,C,K)
  float* out = (float*)d_out;

  static int smem_set = 0;
  if (!smem_set){
    cudaFuncSetAttribute(fps_kernel, cudaFuncAttributeMaxDynamicSharedMemorySize,
                         3*PTS*(int)sizeof(float));
    smem_set = 1;
  }

  bump_epoch_kernel<<<1,1>>>();
  fps_kernel<<<B_ * CL, TPB, 3*PTS*sizeof(float)>>>(xyz, out);
  gather_kernel<<<(B_ * C_ * N_) / 256, 256>>>(feat, out);
}